// round 8
// baseline (speedup 1.0000x reference)
#include <cuda_runtime.h>

// Appro_WAConv2d: depthwise 7x7 conv with mantissa-approximation factor.
//   term = x*w*(f1+f2-1)/(f1*f2) = u*w + s*(w/f2),  u = x/f1, s = x - u
// Packed f32x2: smem {u,s} float2, weights {w, w/f2}; one fma.rn.f32x2/tap.
// Round-8: occupancy push to 4 blocks/SM (49 warps, 77%).
//  - weights loaded as transient LDS.64 broadcasts (1 phase) inside the j
//    loop instead of register-resident rows -> live set ~38 regs (cap 41)
//  - smem row stride 64 pairs: shift/mask indexing, no integer division
//  - phase-1 halo loop fixed 6 iterations, unrolled for LDG MLP

#define B_   4
#define C_   192
#define H_   56
#define W_   56
#define K_   7
#define PAD_ 3
#define HR    28           // output rows per block (half plane)
#define SMROWS 34          // 28 + 2*3 halo rows
#define SMCOLS 62          // 56 + 2*3 halo cols (used)
#define SR    64           // smem row stride in float2 (pow2: shift indexing)
#define NTHR  392
#define CELLS (SMROWS * SR)   // padded loop domain 34*64 = 2176

// mantissa map: a=|v|+1e-7; mant in [1,2); result in [0.75,1.5). Bit trick:
__device__ __forceinline__ float mant_map(float v) {
    float a = fabsf(v) + 1e-7f;
    unsigned b = __float_as_uint(a);
    unsigned m = b & 0x007FFFFFu;
    unsigned e = (m & 0x00400000u) ? 0x3F000000u : 0x3F800000u; // exp 126/127
    return __uint_as_float(m | e);
}

__device__ __forceinline__ unsigned long long fma2(unsigned long long a,
                                                   unsigned long long b,
                                                   unsigned long long c) {
    unsigned long long d;
    asm("fma.rn.f32x2 %0, %1, %2, %3;" : "=l"(d) : "l"(a), "l"(b), "l"(c));
    return d;
}

__device__ __forceinline__ float pairsum(unsigned long long v) {
    return __uint_as_float((unsigned)v) + __uint_as_float((unsigned)(v >> 32));
}

__global__ __launch_bounds__(NTHR, 4)
void waconv_kernel(const float* __restrict__ x,
                   const float* __restrict__ w,
                   float* __restrict__ out) {
    __shared__ __align__(16) float2 sm[CELLS];      // {u, s} interleaved
    __shared__ __align__(16) float2 sw[K_ * 8];     // {w, w/f2}, rows of 8

    const int bid   = blockIdx.x;
    const int plane = bid >> 1;            // b*C + c
    const int h0    = (bid & 1) * HR;      // first output row of this block
    const int c     = plane % C_;
    const float* __restrict__ xp = x + (size_t)plane * (H_ * W_);
    const int tid = threadIdx.x;

    // ---- phase 1a: per-channel packed weights ----
    if (tid < K_ * 8) {
        int j = tid & 7;
        float2 v = make_float2(0.0f, 0.0f);
        if (j < K_) {
            float wv = w[c * (K_ * K_) + (tid >> 3) * K_ + j];
            float f2 = mant_map(wv);
            v = make_float2(wv, __fdividef(wv, f2));
        }
        sw[tid] = v;
    }
    // ---- phase 1b: halo load + mantissa split (shift/mask indexing) ----
#pragma unroll
    for (int k = 0; k < 6; ++k) {
        int idx = tid + k * NTHR;
        if (idx < CELLS) {
            int r = idx >> 6;              // smem row
            int q = idx & 63;              // smem col (pairs)
            if (q < SMCOLS) {
                int iy = h0 + r - PAD_;
                int ix = q - PAD_;
                float v = 0.0f;
                if ((unsigned)iy < H_ && (unsigned)ix < W_) v = xp[iy * W_ + ix];
                float f1 = mant_map(v);
                float u  = __fdividef(v, f1);
                sm[idx] = make_float2(u, v - u);
            }
        }
    }
    __syncthreads();

    // ---- phase 2: 2x2 output tile per thread (14 rows x 28 cols of tiles) ----
    const int ty = tid / 28;               // 0..13
    const int tx = tid - ty * 28;          // 0..27
    const int y0 = ty * 2;                 // local output row
    const int x0 = tx * 2;                 // output col (= packed smem col)

    const unsigned long long* __restrict__ swq = (const unsigned long long*)sw;

    unsigned long long acc00 = 0ull, acc01 = 0ull, acc10 = 0ull, acc11 = 0ull;

#pragma unroll
    for (int t = 0; t < 8; ++t) {          // input halo row = y0 + t
        const unsigned long long* pr =
            (const unsigned long long*)&sm[((y0 + t) << 6) + x0]; // 16B aligned
        unsigned long long p[8];
        ((ulonglong2*)p)[0] = ((const ulonglong2*)pr)[0];
        ((ulonglong2*)p)[1] = ((const ulonglong2*)pr)[1];
        ((ulonglong2*)p)[2] = ((const ulonglong2*)pr)[2];
        ((ulonglong2*)p)[3] = ((const ulonglong2*)pr)[3];

        // oy = 0 uses kernel row i = t (valid t<=6)
        if (t <= 6) {
#pragma unroll
            for (int j = 0; j < K_; ++j) {
                unsigned long long wp = swq[(t << 3) + j];   // LDS.64 broadcast
                acc00 = fma2(p[j],     wp, acc00);
                acc01 = fma2(p[j + 1], wp, acc01);
            }
        }
        // oy = 1 uses kernel row i = t-1 (valid t>=1)
        if (t >= 1) {
#pragma unroll
            for (int j = 0; j < K_; ++j) {
                unsigned long long wp = swq[((t - 1) << 3) + j];
                acc10 = fma2(p[j],     wp, acc10);
                acc11 = fma2(p[j + 1], wp, acc11);
            }
        }
    }

    // ---- epilogue: lane0 + lane1, float2 stores ----
    float* op = out + (size_t)plane * (H_ * W_) + (h0 + y0) * W_ + x0;
    *(float2*)(op)      = make_float2(pairsum(acc00), pairsum(acc01));
    *(float2*)(op + W_) = make_float2(pairsum(acc10), pairsum(acc11));
}

extern "C" void kernel_launch(void* const* d_in, const int* in_sizes, int n_in,
                              void* d_out, int out_size) {
    const float* x  = (const float*)d_in[0];   // (4,192,56,56) f32
    const float* wt = (const float*)d_in[1];   // (192,1,7,7)  f32
    float* out = (float*)d_out;                // (4,192,56,56) f32
    (void)in_sizes; (void)n_in; (void)out_size;
    waconv_kernel<<<B_ * C_ * 2, NTHR>>>(x, wt, out);
}

// round 9
// speedup vs baseline: 1.1892x; 1.1892x over previous
#include <cuda_runtime.h>

// Appro_WAConv2d: depthwise 7x7 conv with mantissa-approximation factor.
//   term = x*w*(f1+f2-1)/(f1*f2) = u*w + s*(w/f2),  u = x/f1, s = x - u
// Packed f32x2: smem {u,s} float2, weights {w, w/f2}; one fma.rn.f32x2/tap.
// Round-9: persistent blocks + double-buffered pipeline.
//   grid = 456 (152 SM x 3 blocks), each block owns ~3-4 half-plane tiles.
//   Per tile iteration: (A) issue next tile's 6 LDGs into regs,
//   (B) compute current tile from sm[buf], (C) mantissa-split regs into
//   sm[buf^1] + next weights, one __syncthreads. GMEM latency, div chains
//   and STS now overlap the FMA/LDS body instead of serializing before it.

#define B_   4
#define C_   192
#define H_   56
#define W_   56
#define K_   7
#define PAD_ 3
#define HR    28            // output rows per tile (half plane)
#define SMROWS 34           // 28 + 2*3 halo rows
#define SMCOLS 62           // 56 + 2*3 halo cols (used)
#define SR    64            // smem row stride in float2 (pow2 indexing)
#define NTHR  392
#define CELLS (SMROWS * SR) // 2176
#define NTILES (B_ * C_ * 2)  // 1536
#define NBLK  456           // 152 SMs * 3 resident blocks

// mantissa map: a=|v|+1e-7; mant in [1,2); result in [0.75,1.5). Bit trick:
__device__ __forceinline__ float mant_map(float v) {
    float a = fabsf(v) + 1e-7f;
    unsigned b = __float_as_uint(a);
    unsigned m = b & 0x007FFFFFu;
    unsigned e = (m & 0x00400000u) ? 0x3F000000u : 0x3F800000u; // exp 126/127
    return __uint_as_float(m | e);
}

__device__ __forceinline__ unsigned long long fma2(unsigned long long a,
                                                   unsigned long long b,
                                                   unsigned long long c) {
    unsigned long long d;
    asm("fma.rn.f32x2 %0, %1, %2, %3;" : "=l"(d) : "l"(a), "l"(b), "l"(c));
    return d;
}

__device__ __forceinline__ float pairsum(unsigned long long v) {
    return __uint_as_float((unsigned)v) + __uint_as_float((unsigned)(v >> 32));
}

__global__ __launch_bounds__(NTHR, 3)
void waconv_kernel(const float* __restrict__ x,
                   const float* __restrict__ w,
                   float* __restrict__ out) {
    __shared__ __align__(16) float2 sm[2][CELLS];     // {u, s} interleaved
    __shared__ __align__(16) float2 sw[2][K_ * 8];    // {w, w/f2}, rows of 8

    const int tid = threadIdx.x;
    const int t0 = (int)(((long long)blockIdx.x       * NTILES) / NBLK);
    const int t1 = (int)(((long long)(blockIdx.x + 1) * NTILES) / NBLK);

    const int ty = tid / 28;               // 0..13
    const int tx = tid - ty * 28;          // 0..27
    const int y0 = ty * 2;
    const int x0 = tx * 2;

    // ---- prologue: fill buffer 0 with tile t0 (direct, stalls once) ----
    {
        const int plane = t0 >> 1;
        const int h0 = (t0 & 1) * HR;
        const float* __restrict__ xp = x + (size_t)plane * (H_ * W_);
        if (tid < K_ * 8) {
            int j = tid & 7;
            float2 v2 = make_float2(0.0f, 0.0f);
            if (j < K_) {
                float wv = w[(plane % C_) * (K_ * K_) + (tid >> 3) * K_ + j];
                float f2 = mant_map(wv);
                v2 = make_float2(wv, __fdividef(wv, f2));
            }
            sw[0][tid] = v2;
        }
#pragma unroll
        for (int kk = 0; kk < 6; ++kk) {
            int idx = tid + kk * NTHR;
            if (idx < CELLS) {
                int r = idx >> 6, q = idx & 63;
                int iy = h0 + r - PAD_, ix = q - PAD_;
                float v = 0.0f;
                if ((unsigned)iy < H_ && (unsigned)ix < W_) v = xp[iy * W_ + ix];
                float f1 = mant_map(v);
                float u  = __fdividef(v, f1);
                sm[0][idx] = make_float2(u, v - u);
            }
        }
    }
    __syncthreads();

    // ---- persistent tile loop ----
    for (int k = t0; k < t1; ++k) {
        const int buf = (k - t0) & 1;
        const int plane = k >> 1;
        const int h0 = (k & 1) * HR;
        const bool more = (k + 1 < t1);

        // stage A: issue next tile's global loads (6 independent LDGs)
        float v[6];
        int nplane = 0;
        if (more) {
            const int nt = k + 1;
            nplane = nt >> 1;
            const int nh0 = (nt & 1) * HR;
            const float* __restrict__ xp = x + (size_t)nplane * (H_ * W_);
#pragma unroll
            for (int kk = 0; kk < 6; ++kk) {
                int idx = tid + kk * NTHR;
                float vv = 0.0f;
                if (idx < CELLS) {
                    int r = idx >> 6, q = idx & 63;
                    int iy = nh0 + r - PAD_, ix = q - PAD_;
                    if ((unsigned)iy < H_ && (unsigned)ix < W_)
                        vv = __ldg(xp + iy * W_ + ix);
                }
                v[kk] = vv;
            }
        }

        // stage B: compute current tile from sm[buf]
        {
            const unsigned long long* __restrict__ swq =
                (const unsigned long long*)sw[buf];
            const float2* __restrict__ smb = sm[buf];
            unsigned long long acc00 = 0ull, acc01 = 0ull,
                               acc10 = 0ull, acc11 = 0ull;
#pragma unroll
            for (int t = 0; t < 8; ++t) {
                const unsigned long long* pr =
                    (const unsigned long long*)&smb[((y0 + t) << 6) + x0];
                unsigned long long p[8];
                ((ulonglong2*)p)[0] = ((const ulonglong2*)pr)[0];
                ((ulonglong2*)p)[1] = ((const ulonglong2*)pr)[1];
                ((ulonglong2*)p)[2] = ((const ulonglong2*)pr)[2];
                ((ulonglong2*)p)[3] = ((const ulonglong2*)pr)[3];
                if (t <= 6) {
#pragma unroll
                    for (int j = 0; j < K_; ++j) {
                        unsigned long long wp = swq[(t << 3) + j];
                        acc00 = fma2(p[j],     wp, acc00);
                        acc01 = fma2(p[j + 1], wp, acc01);
                    }
                }
                if (t >= 1) {
#pragma unroll
                    for (int j = 0; j < K_; ++j) {
                        unsigned long long wp = swq[((t - 1) << 3) + j];
                        acc10 = fma2(p[j],     wp, acc10);
                        acc11 = fma2(p[j + 1], wp, acc11);
                    }
                }
            }
            float* op = out + (size_t)plane * (H_ * W_) + (h0 + y0) * W_ + x0;
            *(float2*)(op)      = make_float2(pairsum(acc00), pairsum(acc01));
            *(float2*)(op + W_) = make_float2(pairsum(acc10), pairsum(acc11));
        }

        // stage C: mantissa-split staged regs into sm[buf^1], next weights
        if (more) {
            if (tid < K_ * 8) {
                int j = tid & 7;
                float2 v2 = make_float2(0.0f, 0.0f);
                if (j < K_) {
                    float wv = w[(nplane % C_) * (K_ * K_) + (tid >> 3) * K_ + j];
                    float f2 = mant_map(wv);
                    v2 = make_float2(wv, __fdividef(wv, f2));
                }
                sw[buf ^ 1][tid] = v2;
            }
#pragma unroll
            for (int kk = 0; kk < 6; ++kk) {
                int idx = tid + kk * NTHR;
                if (idx < CELLS) {
                    float f1 = mant_map(v[kk]);
                    float u  = __fdividef(v[kk], f1);
                    sm[buf ^ 1][idx] = make_float2(u, v[kk] - u);
                }
            }
        }
        __syncthreads();
    }
}

extern "C" void kernel_launch(void* const* d_in, const int* in_sizes, int n_in,
                              void* d_out, int out_size) {
    const float* x  = (const float*)d_in[0];   // (4,192,56,56) f32
    const float* wt = (const float*)d_in[1];   // (192,1,7,7)  f32
    float* out = (float*)d_out;                // (4,192,56,56) f32
    (void)in_sizes; (void)n_in; (void)out_size;
    waconv_kernel<<<NBLK, NTHR>>>(x, wt, out);
}